// round 3
// baseline (speedup 1.0000x reference)
#include <cuda_runtime.h>
#include <cuda_bf16.h>
#include <cstdint>

#define N_NODES 50000
#define N_EDGES 800000
#define IN_CH   256
#define OUT_CH  64
#define NEG_SLOPE 0.2f

// ---------------- scratch (device globals; no allocations allowed) -------------
__device__ float    g_feature[N_NODES * OUT_CH];   // projected features
__device__ float    g_e0[N_NODES];                 // e_pre[:,0]
__device__ float    g_e1[N_NODES];                 // e_pre[:,1]
__device__ float    g_ls[N_NODES];                 // self logit
__device__ unsigned g_menc[N_NODES];               // encoded running max
__device__ float    g_m[N_NODES];                  // decoded max
__device__ float    g_expself[N_NODES];
__device__ float    g_denom[N_NODES];
__device__ float    g_rdenom[N_NODES];
__device__ float    g_elog[N_EDGES];               // edge logit, then exp(edge) in-place

// Monotone float <-> uint mapping so unsigned atomicMax orders like float max.
__device__ __forceinline__ unsigned enc_f(float f) {
    unsigned u = __float_as_uint(f);
    return (u & 0x80000000u) ? ~u : (u | 0x80000000u);
}
__device__ __forceinline__ float dec_f(unsigned u) {
    u = (u & 0x80000000u) ? (u & 0x7fffffffu) : ~u;
    return __uint_as_float(u);
}
__device__ __forceinline__ float lrelu(float v) {
    return v > 0.0f ? v : NEG_SLOPE * v;
}

// ---------------- K1: feature = x @ W^T + b  (64x64 tile SGEMM) ----------------
// 256 threads, TILE_M=64, TILE_N=64 (=OUT_CH), TILE_K=16, 4x4 micro-tiles.
__global__ __launch_bounds__(256) void k_gemm(const float* __restrict__ x,
                                              const float* __restrict__ W,
                                              const float* __restrict__ b) {
    __shared__ float As[16][68];   // [k][m], padded
    __shared__ float Bs[16][68];   // [k][n]

    const int tid  = threadIdx.x;
    const int tx   = tid & 15;          // n-tile index
    const int ty   = tid >> 4;          // m-tile index
    const int r0   = blockIdx.x * 64;
    const int lrow = tid >> 2;          // 0..63 (loader row)
    const int lf4  = tid & 3;           // 0..3  (loader float4 slot)

    float acc[4][4] = {};

    for (int k0 = 0; k0 < IN_CH; k0 += 16) {
        // load A tile (x rows), transposed into As[k][m]
        int gr = r0 + lrow;
        float4 a = make_float4(0.f, 0.f, 0.f, 0.f);
        if (gr < N_NODES)
            a = *(const float4*)(x + (size_t)gr * IN_CH + k0 + lf4 * 4);
        As[lf4 * 4 + 0][lrow] = a.x;
        As[lf4 * 4 + 1][lrow] = a.y;
        As[lf4 * 4 + 2][lrow] = a.z;
        As[lf4 * 4 + 3][lrow] = a.w;
        // load B tile (W rows -> Bs[k][n])
        float4 wv = *(const float4*)(W + (size_t)lrow * IN_CH + k0 + lf4 * 4);
        Bs[lf4 * 4 + 0][lrow] = wv.x;
        Bs[lf4 * 4 + 1][lrow] = wv.y;
        Bs[lf4 * 4 + 2][lrow] = wv.z;
        Bs[lf4 * 4 + 3][lrow] = wv.w;
        __syncthreads();

#pragma unroll
        for (int kk = 0; kk < 16; kk++) {
            float4 av = *(const float4*)&As[kk][ty * 4];
            float4 bv = *(const float4*)&Bs[kk][tx * 4];
            float a4[4] = {av.x, av.y, av.z, av.w};
            float b4[4] = {bv.x, bv.y, bv.z, bv.w};
#pragma unroll
            for (int i = 0; i < 4; i++)
#pragma unroll
                for (int j = 0; j < 4; j++)
                    acc[i][j] += a4[i] * b4[j];
        }
        __syncthreads();
    }

    // epilogue: add bias, store
    float bias[4];
#pragma unroll
    for (int j = 0; j < 4; j++) bias[j] = b[tx * 4 + j];
#pragma unroll
    for (int i = 0; i < 4; i++) {
        int r = r0 + ty * 4 + i;
        if (r < N_NODES) {
            float4 o;
            o.x = acc[i][0] + bias[0];
            o.y = acc[i][1] + bias[1];
            o.z = acc[i][2] + bias[2];
            o.w = acc[i][3] + bias[3];
            *(float4*)&g_feature[(size_t)r * OUT_CH + tx * 4] = o;
        }
    }
}

// ---------------- K2: per-node e_pre, self logit, init max ---------------------
// One warp per node; lane l handles channels l and l+32.
__global__ __launch_bounds__(256) void k_node_pre(const float* __restrict__ att) {
    int w = (blockIdx.x * blockDim.x + threadIdx.x) >> 5;
    int lane = threadIdx.x & 31;
    if (w >= N_NODES) return;
    float f0 = g_feature[(size_t)w * OUT_CH + lane];
    float f1 = g_feature[(size_t)w * OUT_CH + 32 + lane];
    float e0 = f0 * att[lane * 2 + 0] + f1 * att[(lane + 32) * 2 + 0];
    float e1 = f0 * att[lane * 2 + 1] + f1 * att[(lane + 32) * 2 + 1];
#pragma unroll
    for (int o = 16; o; o >>= 1) {
        e0 += __shfl_xor_sync(0xffffffffu, e0, o);
        e1 += __shfl_xor_sync(0xffffffffu, e1, o);
    }
    if (lane == 0) {
        g_e0[w] = e0;
        g_e1[w] = e1;
        float ls = lrelu(e0 + e1);
        g_ls[w] = ls;
        g_menc[w] = enc_f(ls);   // seed max with self-loop logit
    }
}

// ---------------- K3: edge logits + segment max --------------------------------
__global__ __launch_bounds__(256) void k_edge_max(const int* __restrict__ ei) {
    int e = blockIdx.x * blockDim.x + threadIdx.x;
    if (e >= N_EDGES) return;
    int tar = ei[e];
    int src = ei[N_EDGES + e];
    float lg = lrelu(g_e0[tar] + g_e1[src]);
    g_elog[e] = lg;
    atomicMax(&g_menc[tar], enc_f(lg));
}

// ---------------- K4: decode max, exp(self), init denom ------------------------
__global__ __launch_bounds__(256) void k_node_mid() {
    int n = blockIdx.x * blockDim.x + threadIdx.x;
    if (n >= N_NODES) return;
    float m = dec_f(g_menc[n]);
    float es = __expf(g_ls[n] - m);
    g_m[n] = m;
    g_expself[n] = es;
    g_denom[n] = es;
}

// ---------------- K5: exp(edge), accumulate denom ------------------------------
__global__ __launch_bounds__(256) void k_edge_sum(const int* __restrict__ ei) {
    int e = blockIdx.x * blockDim.x + threadIdx.x;
    if (e >= N_EDGES) return;
    int tar = ei[e];
    float ee = __expf(g_elog[e] - g_m[tar]);
    g_elog[e] = ee;   // in-place: now holds exp(edge logit - m)
    atomicAdd(&g_denom[tar], ee);
}

// ---------------- K6: out = alpha_self * feature; store 1/denom ----------------
// 16 threads per node, float4 per thread.
__global__ __launch_bounds__(256) void k_node_out(float* __restrict__ out) {
    int t = blockIdx.x * blockDim.x + threadIdx.x;
    int n = t >> 4;
    if (n >= N_NODES) return;
    int c = (t & 15) * 4;
    float d = g_denom[n];
    float rd = 1.0f / d;
    if ((t & 15) == 0) g_rdenom[n] = rd;
    float as = g_expself[n] * rd;
    float4 f = *(const float4*)&g_feature[(size_t)n * OUT_CH + c];
    float4 o;
    o.x = as * f.x; o.y = as * f.y; o.z = as * f.z; o.w = as * f.w;
    *(float4*)&out[(size_t)n * OUT_CH + c] = o;
}

// ---------------- K7: out[tar] += alpha * feature[src] (vector red) ------------
// 16 threads per edge, float4 gather + red.global.add.v4.f32 scatter.
__global__ __launch_bounds__(256) void k_edge_agg(const int* __restrict__ ei,
                                                  float* __restrict__ out) {
    long long t = (long long)blockIdx.x * blockDim.x + threadIdx.x;
    int e = (int)(t >> 4);
    if (e >= N_EDGES) return;
    int c = ((int)t & 15) * 4;
    int tar = ei[e];
    int src = ei[N_EDGES + e];
    float alpha = g_elog[e] * g_rdenom[tar];
    float4 f = *(const float4*)&g_feature[(size_t)src * OUT_CH + c];
    float* dst = out + (size_t)tar * OUT_CH + c;
    asm volatile("red.global.add.v4.f32 [%0], {%1, %2, %3, %4};"
                 :: "l"(dst), "f"(alpha * f.x), "f"(alpha * f.y),
                    "f"(alpha * f.z), "f"(alpha * f.w)
                 : "memory");
}

// -------------------------------------------------------------------------------
extern "C" void kernel_launch(void* const* d_in, const int* in_sizes, int n_in,
                              void* d_out, int out_size) {
    const float* x   = (const float*)d_in[0];
    const int*   ei  = (const int*)d_in[1];     // edge_index: int32 (JAX x64 disabled)
    const float* W   = (const float*)d_in[2];
    const float* b   = (const float*)d_in[3];
    const float* att = (const float*)d_in[4];
    float* out = (float*)d_out;

    const int T = 256;

    // K1: projection
    k_gemm<<<(N_NODES + 63) / 64, T>>>(x, W, b);
    // K2: per-node attention pre-terms (warp/node)
    k_node_pre<<<(N_NODES * 32 + T - 1) / T, T>>>(att);
    // K3: edge logits + segment max
    k_edge_max<<<(N_EDGES + T - 1) / T, T>>>(ei);
    // K4: per-node max decode + self exp + denom init
    k_node_mid<<<(N_NODES + T - 1) / T, T>>>();
    // K5: edge exp + denom accumulate
    k_edge_sum<<<(N_EDGES + T - 1) / T, T>>>(ei);
    // K6: self-term output init
    k_node_out<<<(N_NODES * 16 + T - 1) / T, T>>>(out);
    // K7: weighted gather-scatter aggregation
    long long agg_threads = (long long)N_EDGES * 16;
    k_edge_agg<<<(unsigned)((agg_threads + T - 1) / T), T>>>(ei, out);
}

// round 5
// speedup vs baseline: 1.1143x; 1.1143x over previous
#include <cuda_runtime.h>
#include <cuda_bf16.h>
#include <cstdint>

#define N_NODES 50000
#define N_EDGES 800000
#define IN_CH   256
#define OUT_CH  64
#define NEG_SLOPE 0.2f

// ---------------- scratch (device globals; no allocations allowed) -------------
__device__ float    g_feature[N_NODES * OUT_CH];
__device__ float    g_e0[N_NODES];
__device__ float    g_e1[N_NODES];
__device__ float    g_ls[N_NODES];
__device__ unsigned g_menc[N_NODES];
__device__ float    g_m[N_NODES];
__device__ float    g_expself[N_NODES];
__device__ float    g_denom[N_NODES];
__device__ float    g_rdenom[N_NODES];
__device__ float    g_elog[N_EDGES];

__device__ __forceinline__ unsigned enc_f(float f) {
    unsigned u = __float_as_uint(f);
    return (u & 0x80000000u) ? ~u : (u | 0x80000000u);
}
__device__ __forceinline__ float dec_f(unsigned u) {
    u = (u & 0x80000000u) ? (u & 0x7fffffffu) : ~u;
    return __uint_as_float(u);
}
__device__ __forceinline__ float lrelu(float v) {
    return v > 0.0f ? v : NEG_SLOPE * v;
}

// pack two floats (even, odd) into bf16x2 (even in low half)
__device__ __forceinline__ uint32_t pack_bf16(float e, float o) {
    uint32_t d;
    asm("cvt.rn.bf16x2.f32 %0, %1, %2;" : "=r"(d) : "f"(o), "f"(e));
    return d;
}
__device__ __forceinline__ float bf16lo_val(uint32_t w) { return __uint_as_float(w << 16); }
__device__ __forceinline__ float bf16hi_val(uint32_t w) { return __uint_as_float(w & 0xFFFF0000u); }

// m16n8k16 row.col bf16 HMMA (target-generic; no tcgen05 on this build)
__device__ __forceinline__ void mma_bf16(float* c, const uint32_t* a, uint32_t b0, uint32_t b1) {
    asm volatile(
        "mma.sync.aligned.m16n8k16.row.col.f32.bf16.bf16.f32 "
        "{%0,%1,%2,%3}, {%4,%5,%6,%7}, {%8,%9}, {%0,%1,%2,%3};"
        : "+f"(c[0]), "+f"(c[1]), "+f"(c[2]), "+f"(c[3])
        : "r"(a[0]), "r"(a[1]), "r"(a[2]), "r"(a[3]), "r"(b0), "r"(b1));
}

// ------------- K1+K2 fused: HMMA bf16 hi/lo projection + attention pre-terms ---
// 8 warps/CTA; warp w -> rows [blk*128 + w*16, +16). B tile (W) in smem bf16x2,
// [64 n][132 words] (k/2 word index, +4 pad words/row -> conflict-free).
__global__ __launch_bounds__(256) void k_gemm_tc(const float* __restrict__ x,
                                                 const float* __restrict__ W,
                                                 const float* __restrict__ b,
                                                 const float* __restrict__ att) {
    __shared__ __align__(16) uint32_t sB[64][132];

    const int tid  = threadIdx.x;
    const int wid  = tid >> 5;
    const int lane = tid & 31;
    const int g    = lane >> 2;       // 0..7
    const int tig  = lane & 3;        // 0..3

    const int base = blockIdx.x * 128 + wid * 16;
    const int r0 = base + g;
    const int r1 = base + g + 8;
    const bool v0 = r0 < N_NODES;
    const bool v1 = r1 < N_NODES;
    const float* xr0 = x + (size_t)(v0 ? r0 : 0) * IN_CH;
    const float* xr1 = x + (size_t)(v1 ? r1 : 0) * IN_CH;

    float acc[8][4];
#pragma unroll
    for (int nt = 0; nt < 8; nt++)
#pragma unroll
        for (int i = 0; i < 4; i++) acc[nt][i] = 0.f;

    // ---- fill sB with W_hi ----
    {
        int n = tid >> 2, q = tid & 3;
        const float4* wr = (const float4*)(W + (size_t)n * IN_CH + q * 64);
#pragma unroll
        for (int i = 0; i < 16; i++) {
            float4 v = wr[i];
            int kw = q * 32 + i * 2;
            sB[n][kw]     = pack_bf16(v.x, v.y);
            sB[n][kw + 1] = pack_bf16(v.z, v.w);
        }
    }
    __syncthreads();

    // ---- pass 1: A_hi*B_hi + A_lo*B_hi ----
#pragma unroll 4
    for (int kc = 0; kc < 16; kc++) {
        const int k0 = kc * 16 + tig * 2;
        float2 a0 = *(const float2*)(xr0 + k0);
        float2 a4 = *(const float2*)(xr0 + k0 + 8);
        float2 c0 = *(const float2*)(xr1 + k0);
        float2 c4 = *(const float2*)(xr1 + k0 + 8);
        uint32_t ah[4], al[4];
        ah[0] = pack_bf16(a0.x, a0.y);
        ah[1] = pack_bf16(c0.x, c0.y);
        ah[2] = pack_bf16(a4.x, a4.y);
        ah[3] = pack_bf16(c4.x, c4.y);
        al[0] = pack_bf16(a0.x - bf16lo_val(ah[0]), a0.y - bf16hi_val(ah[0]));
        al[1] = pack_bf16(c0.x - bf16lo_val(ah[1]), c0.y - bf16hi_val(ah[1]));
        al[2] = pack_bf16(a4.x - bf16lo_val(ah[2]), a4.y - bf16hi_val(ah[2]));
        al[3] = pack_bf16(c4.x - bf16lo_val(ah[3]), c4.y - bf16hi_val(ah[3]));
#pragma unroll
        for (int nt = 0; nt < 8; nt++) {
            uint32_t b0 = sB[nt * 8 + g][kc * 8 + tig];
            uint32_t b1 = sB[nt * 8 + g][kc * 8 + tig + 4];
            mma_bf16(acc[nt], ah, b0, b1);
            mma_bf16(acc[nt], al, b0, b1);
        }
    }
    __syncthreads();

    // ---- refill sB with W_lo ----
    {
        int n = tid >> 2, q = tid & 3;
        const float4* wr = (const float4*)(W + (size_t)n * IN_CH + q * 64);
#pragma unroll
        for (int i = 0; i < 16; i++) {
            float4 v = wr[i];
            int kw = q * 32 + i * 2;
            uint32_t h0 = pack_bf16(v.x, v.y);
            uint32_t h1 = pack_bf16(v.z, v.w);
            sB[n][kw]     = pack_bf16(v.x - bf16lo_val(h0), v.y - bf16hi_val(h0));
            sB[n][kw + 1] = pack_bf16(v.z - bf16lo_val(h1), v.w - bf16hi_val(h1));
        }
    }
    __syncthreads();

    // ---- pass 2: A_hi*B_lo (x re-read; L2-resident) ----
#pragma unroll 4
    for (int kc = 0; kc < 16; kc++) {
        const int k0 = kc * 16 + tig * 2;
        float2 a0 = *(const float2*)(xr0 + k0);
        float2 a4 = *(const float2*)(xr0 + k0 + 8);
        float2 c0 = *(const float2*)(xr1 + k0);
        float2 c4 = *(const float2*)(xr1 + k0 + 8);
        uint32_t ah[4];
        ah[0] = pack_bf16(a0.x, a0.y);
        ah[1] = pack_bf16(c0.x, c0.y);
        ah[2] = pack_bf16(a4.x, a4.y);
        ah[3] = pack_bf16(c4.x, c4.y);
#pragma unroll
        for (int nt = 0; nt < 8; nt++) {
            uint32_t b0 = sB[nt * 8 + g][kc * 8 + tig];
            uint32_t b1 = sB[nt * 8 + g][kc * 8 + tig + 4];
            mma_bf16(acc[nt], ah, b0, b1);
        }
    }

    // ---- epilogue: bias, feature store, fused e0/e1 (old K2) ----
    float e0a = 0.f, e1a = 0.f, e0b = 0.f, e1b = 0.f;
#pragma unroll
    for (int nt = 0; nt < 8; nt++) {
        int col = nt * 8 + tig * 2;
        float bi0 = __ldg(&b[col]);
        float bi1 = __ldg(&b[col + 1]);
        float at00 = __ldg(&att[col * 2 + 0]),     at01 = __ldg(&att[col * 2 + 1]);
        float at10 = __ldg(&att[(col + 1) * 2]),   at11 = __ldg(&att[(col + 1) * 2 + 1]);
        float f0 = acc[nt][0] + bi0, f1 = acc[nt][1] + bi1;   // row r0
        float f2 = acc[nt][2] + bi0, f3 = acc[nt][3] + bi1;   // row r1
        e0a += f0 * at00 + f1 * at10;
        e1a += f0 * at01 + f1 * at11;
        e0b += f2 * at00 + f3 * at10;
        e1b += f2 * at01 + f3 * at11;
        if (v0) *(float2*)&g_feature[(size_t)r0 * OUT_CH + col] = make_float2(f0, f1);
        if (v1) *(float2*)&g_feature[(size_t)r1 * OUT_CH + col] = make_float2(f2, f3);
    }
#pragma unroll
    for (int o = 1; o <= 2; o <<= 1) {
        e0a += __shfl_xor_sync(0xffffffffu, e0a, o);
        e1a += __shfl_xor_sync(0xffffffffu, e1a, o);
        e0b += __shfl_xor_sync(0xffffffffu, e0b, o);
        e1b += __shfl_xor_sync(0xffffffffu, e1b, o);
    }
    if (tig == 0) {
        if (v0) {
            g_e0[r0] = e0a; g_e1[r0] = e1a;
            float ls = lrelu(e0a + e1a);
            g_ls[r0] = ls; g_menc[r0] = enc_f(ls);
        }
        if (v1) {
            g_e0[r1] = e0b; g_e1[r1] = e1b;
            float ls = lrelu(e0b + e1b);
            g_ls[r1] = ls; g_menc[r1] = enc_f(ls);
        }
    }
}

// ---------------- K3: edge logits + segment max --------------------------------
__global__ __launch_bounds__(256) void k_edge_max(const int* __restrict__ ei) {
    int e = blockIdx.x * blockDim.x + threadIdx.x;
    if (e >= N_EDGES) return;
    int tar = ei[e];
    int src = ei[N_EDGES + e];
    float lg = lrelu(g_e0[tar] + g_e1[src]);
    g_elog[e] = lg;
    atomicMax(&g_menc[tar], enc_f(lg));
}

// ---------------- K4: decode max, exp(self), init denom ------------------------
__global__ __launch_bounds__(256) void k_node_mid() {
    int n = blockIdx.x * blockDim.x + threadIdx.x;
    if (n >= N_NODES) return;
    float m = dec_f(g_menc[n]);
    float es = __expf(g_ls[n] - m);
    g_m[n] = m;
    g_expself[n] = es;
    g_denom[n] = es;
}

// ---------------- K5: exp(edge), accumulate denom ------------------------------
__global__ __launch_bounds__(256) void k_edge_sum(const int* __restrict__ ei) {
    int e = blockIdx.x * blockDim.x + threadIdx.x;
    if (e >= N_EDGES) return;
    int tar = ei[e];
    float ee = __expf(g_elog[e] - g_m[tar]);
    g_elog[e] = ee;
    atomicAdd(&g_denom[tar], ee);
}

// ---------------- K6: out = alpha_self * feature; store 1/denom ----------------
__global__ __launch_bounds__(256) void k_node_out(float* __restrict__ out) {
    int t = blockIdx.x * blockDim.x + threadIdx.x;
    int n = t >> 4;
    if (n >= N_NODES) return;
    int c = (t & 15) * 4;
    float d = g_denom[n];
    float rd = 1.0f / d;
    if ((t & 15) == 0) g_rdenom[n] = rd;
    float as = g_expself[n] * rd;
    float4 f = *(const float4*)&g_feature[(size_t)n * OUT_CH + c];
    float4 o;
    o.x = as * f.x; o.y = as * f.y; o.z = as * f.z; o.w = as * f.w;
    *(float4*)&out[(size_t)n * OUT_CH + c] = o;
}

// ---------------- K7: out[tar] += alpha * feature[src] (vector red) ------------
__global__ __launch_bounds__(256) void k_edge_agg(const int* __restrict__ ei,
                                                  float* __restrict__ out) {
    long long t = (long long)blockIdx.x * blockDim.x + threadIdx.x;
    int e = (int)(t >> 4);
    if (e >= N_EDGES) return;
    int c = ((int)t & 15) * 4;
    int tar = ei[e];
    int src = ei[N_EDGES + e];
    float alpha = g_elog[e] * g_rdenom[tar];
    float4 f = *(const float4*)&g_feature[(size_t)src * OUT_CH + c];
    float* dst = out + (size_t)tar * OUT_CH + c;
    asm volatile("red.global.add.v4.f32 [%0], {%1, %2, %3, %4};"
                 :: "l"(dst), "f"(alpha * f.x), "f"(alpha * f.y),
                    "f"(alpha * f.z), "f"(alpha * f.w)
                 : "memory");
}

// -------------------------------------------------------------------------------
extern "C" void kernel_launch(void* const* d_in, const int* in_sizes, int n_in,
                              void* d_out, int out_size) {
    const float* x   = (const float*)d_in[0];
    const int*   ei  = (const int*)d_in[1];   // int32 (JAX x64 disabled)
    const float* W   = (const float*)d_in[2];
    const float* b   = (const float*)d_in[3];
    const float* att = (const float*)d_in[4];
    float* out = (float*)d_out;

    const int T = 256;

    // K1+K2 fused: HMMA projection + attention pre-terms
    k_gemm_tc<<<(N_NODES + 127) / 128, T>>>(x, W, b, att);
    // K3: edge logits + segment max
    k_edge_max<<<(N_EDGES + T - 1) / T, T>>>(ei);
    // K4: per-node max decode + self exp + denom init
    k_node_mid<<<(N_NODES + T - 1) / T, T>>>();
    // K5: edge exp + denom accumulate
    k_edge_sum<<<(N_EDGES + T - 1) / T, T>>>(ei);
    // K6: self-term output init
    k_node_out<<<(N_NODES * 16 + T - 1) / T, T>>>(out);
    // K7: weighted gather-scatter aggregation
    long long agg_threads = (long long)N_EDGES * 16;
    k_edge_agg<<<(unsigned)((agg_threads + T - 1) / T), T>>>(ei, out);
}

// round 6
// speedup vs baseline: 1.2181x; 1.0932x over previous
#include <cuda_runtime.h>
#include <cuda_bf16.h>
#include <cstdint>

#define N_NODES 50000
#define N_EDGES 800000
#define IN_CH   256
#define OUT_CH  64
#define NEG_SLOPE 0.2f

// ---------------- scratch (device globals; no allocations allowed) -------------
__device__ float g_feature[N_NODES * OUT_CH];
__device__ float g_e0[N_NODES];
__device__ float g_e1[N_NODES];
__device__ float g_denom[N_NODES];

__device__ __forceinline__ float lrelu(float v) {
    return v > 0.0f ? v : NEG_SLOPE * v;
}

// pack two floats (even, odd) into bf16x2 (even in low half)
__device__ __forceinline__ uint32_t pack_bf16(float e, float o) {
    uint32_t d;
    asm("cvt.rn.bf16x2.f32 %0, %1, %2;" : "=r"(d) : "f"(o), "f"(e));
    return d;
}
__device__ __forceinline__ float bf16lo_val(uint32_t w) { return __uint_as_float(w << 16); }
__device__ __forceinline__ float bf16hi_val(uint32_t w) { return __uint_as_float(w & 0xFFFF0000u); }

// m16n8k16 row.col bf16 HMMA (target-generic; tcgen05 unavailable on this build)
__device__ __forceinline__ void mma_bf16(float* c, const uint32_t* a, uint32_t b0, uint32_t b1) {
    asm volatile(
        "mma.sync.aligned.m16n8k16.row.col.f32.bf16.bf16.f32 "
        "{%0,%1,%2,%3}, {%4,%5,%6,%7}, {%8,%9}, {%0,%1,%2,%3};"
        : "+f"(c[0]), "+f"(c[1]), "+f"(c[2]), "+f"(c[3])
        : "r"(a[0]), "r"(a[1]), "r"(a[2]), "r"(a[3]), "r"(b0), "r"(b1));
}

// ------------- K1: HMMA bf16 hi/lo projection + attention pre-terms + self seed
// 8 warps/CTA; warp w -> rows [blk*128 + w*16, +16). No-max softmax: epilogue
// writes out = exp(ls)*feature (self term) and denom = exp(ls).
__global__ __launch_bounds__(256) void k_gemm_tc(const float* __restrict__ x,
                                                 const float* __restrict__ W,
                                                 const float* __restrict__ b,
                                                 const float* __restrict__ att,
                                                 float* __restrict__ out) {
    __shared__ __align__(16) uint32_t sB[64][132];

    const int tid  = threadIdx.x;
    const int wid  = tid >> 5;
    const int lane = tid & 31;
    const int g    = lane >> 2;       // 0..7
    const int tig  = lane & 3;        // 0..3

    const int base = blockIdx.x * 128 + wid * 16;
    const int r0 = base + g;
    const int r1 = base + g + 8;
    const bool v0 = r0 < N_NODES;
    const bool v1 = r1 < N_NODES;
    const float* xr0 = x + (size_t)(v0 ? r0 : 0) * IN_CH;
    const float* xr1 = x + (size_t)(v1 ? r1 : 0) * IN_CH;

    float acc[8][4];
#pragma unroll
    for (int nt = 0; nt < 8; nt++)
#pragma unroll
        for (int i = 0; i < 4; i++) acc[nt][i] = 0.f;

    // ---- fill sB with W_hi ----
    {
        int n = tid >> 2, q = tid & 3;
        const float4* wr = (const float4*)(W + (size_t)n * IN_CH + q * 64);
#pragma unroll
        for (int i = 0; i < 16; i++) {
            float4 v = wr[i];
            int kw = q * 32 + i * 2;
            sB[n][kw]     = pack_bf16(v.x, v.y);
            sB[n][kw + 1] = pack_bf16(v.z, v.w);
        }
    }
    __syncthreads();

    // ---- pass 1: A_hi*B_hi + A_lo*B_hi ----
#pragma unroll 4
    for (int kc = 0; kc < 16; kc++) {
        const int k0 = kc * 16 + tig * 2;
        float2 a0 = *(const float2*)(xr0 + k0);
        float2 a4 = *(const float2*)(xr0 + k0 + 8);
        float2 c0 = *(const float2*)(xr1 + k0);
        float2 c4 = *(const float2*)(xr1 + k0 + 8);
        uint32_t ah[4], al[4];
        ah[0] = pack_bf16(a0.x, a0.y);
        ah[1] = pack_bf16(c0.x, c0.y);
        ah[2] = pack_bf16(a4.x, a4.y);
        ah[3] = pack_bf16(c4.x, c4.y);
        al[0] = pack_bf16(a0.x - bf16lo_val(ah[0]), a0.y - bf16hi_val(ah[0]));
        al[1] = pack_bf16(c0.x - bf16lo_val(ah[1]), c0.y - bf16hi_val(ah[1]));
        al[2] = pack_bf16(a4.x - bf16lo_val(ah[2]), a4.y - bf16hi_val(ah[2]));
        al[3] = pack_bf16(c4.x - bf16lo_val(ah[3]), c4.y - bf16hi_val(ah[3]));
#pragma unroll
        for (int nt = 0; nt < 8; nt++) {
            uint32_t b0 = sB[nt * 8 + g][kc * 8 + tig];
            uint32_t b1 = sB[nt * 8 + g][kc * 8 + tig + 4];
            mma_bf16(acc[nt], ah, b0, b1);
            mma_bf16(acc[nt], al, b0, b1);
        }
    }
    __syncthreads();

    // ---- refill sB with W_lo ----
    {
        int n = tid >> 2, q = tid & 3;
        const float4* wr = (const float4*)(W + (size_t)n * IN_CH + q * 64);
#pragma unroll
        for (int i = 0; i < 16; i++) {
            float4 v = wr[i];
            int kw = q * 32 + i * 2;
            uint32_t h0 = pack_bf16(v.x, v.y);
            uint32_t h1 = pack_bf16(v.z, v.w);
            sB[n][kw]     = pack_bf16(v.x - bf16lo_val(h0), v.y - bf16hi_val(h0));
            sB[n][kw + 1] = pack_bf16(v.z - bf16lo_val(h1), v.w - bf16hi_val(h1));
        }
    }
    __syncthreads();

    // ---- pass 2: A_hi*B_lo (x re-read; L2-resident) ----
#pragma unroll 4
    for (int kc = 0; kc < 16; kc++) {
        const int k0 = kc * 16 + tig * 2;
        float2 a0 = *(const float2*)(xr0 + k0);
        float2 a4 = *(const float2*)(xr0 + k0 + 8);
        float2 c0 = *(const float2*)(xr1 + k0);
        float2 c4 = *(const float2*)(xr1 + k0 + 8);
        uint32_t ah[4];
        ah[0] = pack_bf16(a0.x, a0.y);
        ah[1] = pack_bf16(c0.x, c0.y);
        ah[2] = pack_bf16(a4.x, a4.y);
        ah[3] = pack_bf16(c4.x, c4.y);
#pragma unroll
        for (int nt = 0; nt < 8; nt++) {
            uint32_t b0 = sB[nt * 8 + g][kc * 8 + tig];
            uint32_t b1 = sB[nt * 8 + g][kc * 8 + tig + 4];
            mma_bf16(acc[nt], ah, b0, b1);
        }
    }

    // ---- epilogue: bias into acc, e0/e1 reduce, self-term seed ----
    float e0a = 0.f, e1a = 0.f, e0b = 0.f, e1b = 0.f;
#pragma unroll
    for (int nt = 0; nt < 8; nt++) {
        int col = nt * 8 + tig * 2;
        float bi0 = __ldg(&b[col]);
        float bi1 = __ldg(&b[col + 1]);
        float at00 = __ldg(&att[col * 2 + 0]),   at01 = __ldg(&att[col * 2 + 1]);
        float at10 = __ldg(&att[(col + 1) * 2]), at11 = __ldg(&att[(col + 1) * 2 + 1]);
        acc[nt][0] += bi0; acc[nt][1] += bi1;   // row r0
        acc[nt][2] += bi0; acc[nt][3] += bi1;   // row r1
        e0a += acc[nt][0] * at00 + acc[nt][1] * at10;
        e1a += acc[nt][0] * at01 + acc[nt][1] * at11;
        e0b += acc[nt][2] * at00 + acc[nt][3] * at10;
        e1b += acc[nt][2] * at01 + acc[nt][3] * at11;
    }
#pragma unroll
    for (int o = 1; o <= 2; o <<= 1) {
        e0a += __shfl_xor_sync(0xffffffffu, e0a, o);
        e1a += __shfl_xor_sync(0xffffffffu, e1a, o);
        e0b += __shfl_xor_sync(0xffffffffu, e0b, o);
        e1b += __shfl_xor_sync(0xffffffffu, e1b, o);
    }
    const float esa = __expf(lrelu(e0a + e1a));   // same in all 4 lanes of quad
    const float esb = __expf(lrelu(e0b + e1b));
#pragma unroll
    for (int nt = 0; nt < 8; nt++) {
        int col = nt * 8 + tig * 2;
        if (v0) {
            *(float2*)&g_feature[(size_t)r0 * OUT_CH + col] = make_float2(acc[nt][0], acc[nt][1]);
            *(float2*)&out[(size_t)r0 * OUT_CH + col] = make_float2(esa * acc[nt][0], esa * acc[nt][1]);
        }
        if (v1) {
            *(float2*)&g_feature[(size_t)r1 * OUT_CH + col] = make_float2(acc[nt][2], acc[nt][3]);
            *(float2*)&out[(size_t)r1 * OUT_CH + col] = make_float2(esb * acc[nt][2], esb * acc[nt][3]);
        }
    }
    if (tig == 0) {
        if (v0) { g_e0[r0] = e0a; g_e1[r0] = e1a; g_denom[r0] = esa; }
        if (v1) { g_e0[r1] = e0b; g_e1[r1] = e1b; g_denom[r1] = esb; }
    }
}

// ------------- K2: single fused edge pass --------------------------------------
// 16 threads/edge. Leader computes ee = exp(lrelu(e0[tar]+e1[src])), shfl
// broadcast; denom RED + unnormalized message RED into out.
__global__ __launch_bounds__(256) void k_edge(const int* __restrict__ ei,
                                              float* __restrict__ out) {
    const unsigned t = blockIdx.x * 256u + threadIdx.x;
    const int e = (int)(t >> 4);                 // grid sized so e < N_EDGES always
    const int lane = threadIdx.x & 31;
    const int sub  = lane & 15;

    int tar = 0, src = 0;
    float ee = 0.f;
    if (sub == 0) {
        tar = __ldg(&ei[e]);
        src = __ldg(&ei[N_EDGES + e]);
        ee = __expf(lrelu(g_e0[tar] + g_e1[src]));
    }
    const int bl = lane & 16;                    // broadcast source: lane 0 / 16
    tar = __shfl_sync(0xffffffffu, tar, bl);
    src = __shfl_sync(0xffffffffu, src, bl);
    ee  = __shfl_sync(0xffffffffu, ee,  bl);

    if (sub == 0) {
        asm volatile("red.global.add.f32 [%0], %1;" :: "l"(&g_denom[tar]), "f"(ee) : "memory");
    }
    const int c = sub * 4;
    float4 f = *(const float4*)&g_feature[(size_t)src * OUT_CH + c];
    float* dst = out + (size_t)tar * OUT_CH + c;
    asm volatile("red.global.add.v4.f32 [%0], {%1, %2, %3, %4};"
                 :: "l"(dst), "f"(ee * f.x), "f"(ee * f.y),
                    "f"(ee * f.z), "f"(ee * f.w)
                 : "memory");
}

// ------------- K3: normalize out by 1/denom ------------------------------------
__global__ __launch_bounds__(256) void k_norm(float* __restrict__ out) {
    int t = blockIdx.x * blockDim.x + threadIdx.x;
    int n = t >> 4;
    if (n >= N_NODES) return;
    int c = (t & 15) * 4;
    float rd = 1.0f / g_denom[n];
    float4 o = *(const float4*)&out[(size_t)n * OUT_CH + c];
    o.x *= rd; o.y *= rd; o.z *= rd; o.w *= rd;
    *(float4*)&out[(size_t)n * OUT_CH + c] = o;
}

// -------------------------------------------------------------------------------
extern "C" void kernel_launch(void* const* d_in, const int* in_sizes, int n_in,
                              void* d_out, int out_size) {
    const float* x   = (const float*)d_in[0];
    const int*   ei  = (const int*)d_in[1];   // int32 (JAX x64 disabled)
    const float* W   = (const float*)d_in[2];
    const float* b   = (const float*)d_in[3];
    const float* att = (const float*)d_in[4];
    float* out = (float*)d_out;

    const int T = 256;

    // K1: HMMA projection + attention pre-terms + self-term seed
    k_gemm_tc<<<(N_NODES + 127) / 128, T>>>(x, W, b, att, out);
    // K2: fused edge softmax + aggregation (16 threads/edge; 800000*16/256 = 50000 blocks)
    k_edge<<<(N_EDGES * 16) / T, T>>>(ei, out);
    // K3: normalize
    k_norm<<<(N_NODES * 16 + T - 1) / T, T>>>(out);
}

// round 7
// speedup vs baseline: 1.4110x; 1.1583x over previous
#include <cuda_runtime.h>
#include <cuda_bf16.h>
#include <cstdint>

#define N_NODES 50000
#define N_EDGES 800000
#define IN_CH   256
#define OUT_CH  64
#define NEG_SLOPE 0.2f

// ---------------- scratch (device globals; no allocations allowed) -------------
__device__ float    g_feature[N_NODES * OUT_CH];
__device__ float    g_e0[N_NODES];
__device__ float    g_e1[N_NODES];
__device__ float    g_denom[N_NODES];
__device__ uint32_t g_Wh[2 * 64 * 64];   // [half][n][kw] bf16x2 hi
__device__ uint32_t g_Wl[2 * 64 * 64];   // [half][n][kw] bf16x2 lo

__device__ __forceinline__ float lrelu(float v) {
    return v > 0.0f ? v : NEG_SLOPE * v;
}

// pack two floats (even, odd) into bf16x2 (even in low half)
__device__ __forceinline__ uint32_t pack_bf16(float e, float o) {
    uint32_t d;
    asm("cvt.rn.bf16x2.f32 %0, %1, %2;" : "=r"(d) : "f"(o), "f"(e));
    return d;
}
__device__ __forceinline__ float bf16lo_val(uint32_t w) { return __uint_as_float(w << 16); }
__device__ __forceinline__ float bf16hi_val(uint32_t w) { return __uint_as_float(w & 0xFFFF0000u); }

// m16n8k16 row.col bf16 HMMA (target-generic; tcgen05 unavailable on this build)
__device__ __forceinline__ void mma_bf16(float* c, const uint32_t* a, uint32_t b0, uint32_t b1) {
    asm volatile(
        "mma.sync.aligned.m16n8k16.row.col.f32.bf16.bf16.f32 "
        "{%0,%1,%2,%3}, {%4,%5,%6,%7}, {%8,%9}, {%0,%1,%2,%3};"
        : "+f"(c[0]), "+f"(c[1]), "+f"(c[2]), "+f"(c[3])
        : "r"(a[0]), "r"(a[1]), "r"(a[2]), "r"(a[3]), "r"(b0), "r"(b1));
}

// ------------- K0: one-time W -> bf16 hi/lo conversion -------------------------
// Layout g_Wh/g_Wl: idx = half*4096 + n*64 + j, word j covers k = half*128 + 2j.
__global__ __launch_bounds__(256) void k_wconv(const float* __restrict__ W) {
    int idx = blockIdx.x * 256 + threadIdx.x;    // 0..8191
    int half = idx >> 12, rem = idx & 4095;
    int n = rem >> 6, j = rem & 63;
    int k = half * 128 + j * 2;
    float w0 = W[n * 256 + k], w1 = W[n * 256 + k + 1];
    uint32_t h = pack_bf16(w0, w1);
    uint32_t l = pack_bf16(w0 - bf16lo_val(h), w1 - bf16hi_val(h));
    g_Wh[idx] = h;
    g_Wl[idx] = l;
}

// ------------- K1: HMMA bf16 hi/lo projection, single x pass -------------------
// 128 threads = 4 warps; warp w -> rows [blk*64 + w*16, +16). K split in two
// halves of 128; per half both Bh and Bl half-tiles live in smem, so each kc
// does Ah*Bh + Al*Bh + Ah*Bl with one global read of x.
__global__ __launch_bounds__(128, 5) void k_gemm_tc(const float* __restrict__ x,
                                                    const float* __restrict__ b,
                                                    const float* __restrict__ att,
                                                    float* __restrict__ out) {
    __shared__ __align__(16) uint32_t sBh[64][68];
    __shared__ __align__(16) uint32_t sBl[64][68];

    const int tid  = threadIdx.x;
    const int wid  = tid >> 5;
    const int lane = tid & 31;
    const int g    = lane >> 2;       // 0..7
    const int tig  = lane & 3;        // 0..3

    const int base = blockIdx.x * 64 + wid * 16;
    const int r0 = base + g;
    const int r1 = base + g + 8;
    const bool v0 = r0 < N_NODES;
    const bool v1 = r1 < N_NODES;
    const float* xr0 = x + (size_t)(v0 ? r0 : 0) * IN_CH;
    const float* xr1 = x + (size_t)(v1 ? r1 : 0) * IN_CH;

    float acc[8][4];
#pragma unroll
    for (int nt = 0; nt < 8; nt++)
#pragma unroll
        for (int i = 0; i < 4; i++) acc[nt][i] = 0.f;

    const int cn   = tid >> 1;        // copy row 0..63
    const int part = tid & 1;         // half-row 0..1

#pragma unroll
    for (int half = 0; half < 2; half++) {
        // ---- fill smem: straight uint4 copy of pre-converted Bh/Bl half-tiles --
        if (half) __syncthreads();
        {
            const uint4* srcH = (const uint4*)&g_Wh[half * 4096 + cn * 64 + part * 32];
            const uint4* srcL = (const uint4*)&g_Wl[half * 4096 + cn * 64 + part * 32];
            uint4* dstH = (uint4*)&sBh[cn][part * 32];
            uint4* dstL = (uint4*)&sBl[cn][part * 32];
#pragma unroll
            for (int i = 0; i < 8; i++) { dstH[i] = srcH[i]; dstL[i] = srcL[i]; }
        }
        __syncthreads();

#pragma unroll
        for (int kc = 0; kc < 8; kc++) {
            const int k0 = half * 128 + kc * 16 + tig * 2;
            float2 a0 = *(const float2*)(xr0 + k0);
            float2 a4 = *(const float2*)(xr0 + k0 + 8);
            float2 c0 = *(const float2*)(xr1 + k0);
            float2 c4 = *(const float2*)(xr1 + k0 + 8);
            uint32_t ah[4], al[4];
            ah[0] = pack_bf16(a0.x, a0.y);
            ah[1] = pack_bf16(c0.x, c0.y);
            ah[2] = pack_bf16(a4.x, a4.y);
            ah[3] = pack_bf16(c4.x, c4.y);
            al[0] = pack_bf16(a0.x - bf16lo_val(ah[0]), a0.y - bf16hi_val(ah[0]));
            al[1] = pack_bf16(c0.x - bf16lo_val(ah[1]), c0.y - bf16hi_val(ah[1]));
            al[2] = pack_bf16(a4.x - bf16lo_val(ah[2]), a4.y - bf16hi_val(ah[2]));
            al[3] = pack_bf16(c4.x - bf16lo_val(ah[3]), c4.y - bf16hi_val(ah[3]));
#pragma unroll
            for (int nt = 0; nt < 8; nt++) {
                const int n = nt * 8 + g;
                const int kw = kc * 8 + tig;
                uint32_t bh0 = sBh[n][kw], bh1 = sBh[n][kw + 4];
                uint32_t bl0 = sBl[n][kw], bl1 = sBl[n][kw + 4];
                mma_bf16(acc[nt], ah, bh0, bh1);
                mma_bf16(acc[nt], al, bh0, bh1);
                mma_bf16(acc[nt], ah, bl0, bl1);
            }
        }
    }

    // ---- epilogue: bias into acc, e0/e1 reduce, self-term seed ----
    float e0a = 0.f, e1a = 0.f, e0b = 0.f, e1b = 0.f;
#pragma unroll
    for (int nt = 0; nt < 8; nt++) {
        int col = nt * 8 + tig * 2;
        float bi0 = __ldg(&b[col]);
        float bi1 = __ldg(&b[col + 1]);
        float at00 = __ldg(&att[col * 2 + 0]),   at01 = __ldg(&att[col * 2 + 1]);
        float at10 = __ldg(&att[(col + 1) * 2]), at11 = __ldg(&att[(col + 1) * 2 + 1]);
        acc[nt][0] += bi0; acc[nt][1] += bi1;   // row r0
        acc[nt][2] += bi0; acc[nt][3] += bi1;   // row r1
        e0a += acc[nt][0] * at00 + acc[nt][1] * at10;
        e1a += acc[nt][0] * at01 + acc[nt][1] * at11;
        e0b += acc[nt][2] * at00 + acc[nt][3] * at10;
        e1b += acc[nt][2] * at01 + acc[nt][3] * at11;
    }
#pragma unroll
    for (int o = 1; o <= 2; o <<= 1) {
        e0a += __shfl_xor_sync(0xffffffffu, e0a, o);
        e1a += __shfl_xor_sync(0xffffffffu, e1a, o);
        e0b += __shfl_xor_sync(0xffffffffu, e0b, o);
        e1b += __shfl_xor_sync(0xffffffffu, e1b, o);
    }
    const float esa = __expf(lrelu(e0a + e1a));   // same in all 4 lanes of quad
    const float esb = __expf(lrelu(e0b + e1b));
#pragma unroll
    for (int nt = 0; nt < 8; nt++) {
        int col = nt * 8 + tig * 2;
        if (v0) {
            *(float2*)&g_feature[(size_t)r0 * OUT_CH + col] = make_float2(acc[nt][0], acc[nt][1]);
            *(float2*)&out[(size_t)r0 * OUT_CH + col] = make_float2(esa * acc[nt][0], esa * acc[nt][1]);
        }
        if (v1) {
            *(float2*)&g_feature[(size_t)r1 * OUT_CH + col] = make_float2(acc[nt][2], acc[nt][3]);
            *(float2*)&out[(size_t)r1 * OUT_CH + col] = make_float2(esb * acc[nt][2], esb * acc[nt][3]);
        }
    }
    if (tig == 0) {
        if (v0) { g_e0[r0] = e0a; g_e1[r0] = e1a; g_denom[r0] = esa; }
        if (v1) { g_e0[r1] = e0b; g_e1[r1] = e1b; g_denom[r1] = esb; }
    }
}

// ------------- K2: single fused edge pass --------------------------------------
// 16 threads/edge. Leader computes ee = exp(lrelu(e0[tar]+e1[src])), shfl
// broadcast; denom RED + unnormalized message RED into out.
__global__ __launch_bounds__(256) void k_edge(const int* __restrict__ ei,
                                              float* __restrict__ out) {
    const unsigned t = blockIdx.x * 256u + threadIdx.x;
    const int e = (int)(t >> 4);                 // grid sized so e < N_EDGES always
    const int lane = threadIdx.x & 31;
    const int sub  = lane & 15;

    int tar = 0, src = 0;
    float ee = 0.f;
    if (sub == 0) {
        tar = __ldg(&ei[e]);
        src = __ldg(&ei[N_EDGES + e]);
        ee = __expf(lrelu(g_e0[tar] + g_e1[src]));
    }
    const int bl = lane & 16;                    // broadcast source: lane 0 / 16
    tar = __shfl_sync(0xffffffffu, tar, bl);
    src = __shfl_sync(0xffffffffu, src, bl);
    ee  = __shfl_sync(0xffffffffu, ee,  bl);

    if (sub == 0) {
        asm volatile("red.global.add.f32 [%0], %1;" :: "l"(&g_denom[tar]), "f"(ee) : "memory");
    }
    const int c = sub * 4;
    float4 f = *(const float4*)&g_feature[(size_t)src * OUT_CH + c];
    float* dst = out + (size_t)tar * OUT_CH + c;
    asm volatile("red.global.add.v4.f32 [%0], {%1, %2, %3, %4};"
                 :: "l"(dst), "f"(ee * f.x), "f"(ee * f.y),
                    "f"(ee * f.z), "f"(ee * f.w)
                 : "memory");
}

// ------------- K3: normalize out by 1/denom ------------------------------------
__global__ __launch_bounds__(256) void k_norm(float* __restrict__ out) {
    int t = blockIdx.x * blockDim.x + threadIdx.x;
    int n = t >> 4;
    if (n >= N_NODES) return;
    int c = (t & 15) * 4;
    float rd = 1.0f / g_denom[n];
    float4 o = *(const float4*)&out[(size_t)n * OUT_CH + c];
    o.x *= rd; o.y *= rd; o.z *= rd; o.w *= rd;
    *(float4*)&out[(size_t)n * OUT_CH + c] = o;
}

// -------------------------------------------------------------------------------
extern "C" void kernel_launch(void* const* d_in, const int* in_sizes, int n_in,
                              void* d_out, int out_size) {
    const float* x   = (const float*)d_in[0];
    const int*   ei  = (const int*)d_in[1];   // int32 (JAX x64 disabled)
    const float* W   = (const float*)d_in[2];
    const float* b   = (const float*)d_in[3];
    const float* att = (const float*)d_in[4];
    float* out = (float*)d_out;

    // K0: one-time W -> bf16 hi/lo (8192 words)
    k_wconv<<<32, 256>>>(W);
    // K1: HMMA projection + attention pre-terms + self-term seed
    k_gemm_tc<<<(N_NODES + 63) / 64, 128>>>(x, b, att, out);
    // K2: fused edge softmax + aggregation (16 threads/edge)
    k_edge<<<(N_EDGES * 16) / 256, 256>>>(ei, out);
    // K3: normalize
    k_norm<<<(N_NODES * 16 + 255) / 256, 256>>>(out);
}